// round 6
// baseline (speedup 1.0000x reference)
#include <cuda_runtime.h>
#include <math.h>

#define NODE  400
#define TRS   40
#define STEPS 10
#define NSTEP (TRS * STEPS)
#define OUTN  64
#define DMAXC 500
#define KBUF  512
#define DTF   0.1f
#define LOG2E 1.4426950408889634f

#define NPB   8        // nodes (warps) per sim block
#define WN    904      // timeline ring: 500 initial + 400 steps (+pad)
// per-node dynamic smem slot layout (bytes)
#define OFF_KSM  0                        // float4[KBUF] = 8192
#define OFF_W    (KBUF * 16)              // float[WN]    = 3616
#define OFF_ES   (OFF_W + WN * 4)         // float[NSTEP] = 1600
#define NODE_SMEM 13440
#define SIM_SMEM (NODE_SMEM * NPB)        // 107520

// ---- persistent scratch (device globals; no allocation) ----
__device__ float  g_rowSS[3 * NODE];
__device__ float  g_invnorm[3];       // [b, f, l]
__device__ float  g_rs[NODE * 3];     // raw row sums [b,f,l] per node
__device__ float4 g_K4[NODE * KBUF];  // per-node delay histogram (x=b,y=f,z=l)
__device__ int    g_ndmax[NODE];
__device__ float  g_colmean[NODE];
__device__ float  g_Vsnap[TRS * NODE];

__device__ __forceinline__ float reluf(float x) { return x > 0.f ? x : 0.f; }
__device__ __forceinline__ float ex2f(float x) { float y; asm("ex2.approx.f32 %0,%1;" : "=f"(y) : "f"(x)); return y; }
__device__ __forceinline__ float rcpf(float x) { float y; asm("rcp.approx.f32 %0,%1;" : "=f"(y) : "f"(x)); return y; }

// ---------------------------------------------------------------------------
// PREP: per-node weights, row sums, row sum-of-squares, delay histogram, dmax.
// ---------------------------------------------------------------------------
__global__ void __launch_bounds__(128) prep_kernel(
    const float* __restrict__ wbb, const float* __restrict__ wff,
    const float* __restrict__ wll, const float* __restrict__ sc,
    const float* __restrict__ dist, const float* __restrict__ theta)
{
    int i = blockIdx.x;
    int tid = threadIdx.x;
    int w = tid >> 5, lane = tid & 31;
    __shared__ float4 w4[NODE];        // 6.4 KB
    __shared__ int    dly[NODE];       // 1.6 KB
    __shared__ float4 H[4][KBUF];      // 32 KB private histograms
    __shared__ float  red[6][128];     // 3 KB
    __shared__ int    dred[4];

    float mu = 0.1f + reluf(theta[20]);
    float ssb = 0.f, ssf = 0.f, ssl = 0.f, rb = 0.f, rf = 0.f, rl = 0.f;
    for (int j = tid; j < NODE; j += 128) {
        float scij = sc[i * NODE + j];
        float wb = __expf(wbb[i * NODE + j]) * scij;
        float wf = __expf(wff[i * NODE + j]) * scij;
        float wl = 0.5f * (__expf(wll[i * NODE + j]) * scij +
                           __expf(wll[j * NODE + i]) * sc[j * NODE + i]);
        int d = (int)(dist[i * NODE + j] / mu);   // accurate division like reference
        if (d < 0) d = 0;
        if (d > DMAXC - 1) d = DMAXC - 1;
        w4[j] = make_float4(wb, wf, wl, 0.f);
        dly[j] = d;
        ssb += wb * wb; ssf += wf * wf; ssl += wl * wl;
        rb += wb; rf += wf; rl += wl;
    }
    for (int d = tid; d < KBUF; d += 128) {
        float4 z = make_float4(0.f, 0.f, 0.f, 0.f);
        H[0][d] = z; H[1][d] = z; H[2][d] = z; H[3][d] = z;
    }
    red[0][tid] = ssb; red[1][tid] = ssf; red[2][tid] = ssl;
    red[3][tid] = rb;  red[4][tid] = rf;  red[5][tid] = rl;
    __syncthreads();
    for (int off = 64; off; off >>= 1) {
        if (tid < off) {
#pragma unroll
            for (int c = 0; c < 6; c++) red[c][tid] += red[c][tid + off];
        }
        __syncthreads();
    }
    if (tid == 0) {
        g_rowSS[0 * NODE + i] = red[0][0];
        g_rowSS[1 * NODE + i] = red[1][0];
        g_rowSS[2 * NODE + i] = red[2][0];
        g_rs[i * 3 + 0] = red[3][0];
        g_rs[i * 3 + 1] = red[4][0];
        g_rs[i * 3 + 2] = red[5][0];
    }

    // histogram: warp w scans j in [100w, 100w+100); lane owns (d&31)==lane bins
    int dmx = 0;
    int j0 = w * (NODE / 4);
    for (int jj = 0; jj < NODE / 4; jj++) {
        int j = j0 + jj;
        int d = dly[j];
        if ((d & 31) == lane) {
            float4 wv = w4[j];
            H[w][d].x += wv.x; H[w][d].y += wv.y; H[w][d].z += wv.z;
            dmx = d > dmx ? d : dmx;
        }
    }
#pragma unroll
    for (int off = 16; off; off >>= 1) dmx = max(dmx, __shfl_xor_sync(0xffffffffu, dmx, off));
    if (lane == 0) dred[w] = dmx;
    __syncthreads();

    float4* Kg = g_K4 + (size_t)i * KBUF;
    for (int d = tid; d < KBUF; d += 128) {
        float4 a = H[0][d], b = H[1][d], c = H[2][d], e = H[3][d];
        float4 r;
        r.x = ((a.x + b.x) + c.x) + e.x;
        r.y = ((a.y + b.y) + c.y) + e.y;
        r.z = ((a.z + b.z) + c.z) + e.z;
        r.w = 0.f;
        Kg[d] = r;
    }
    if (tid == 0) g_ndmax[i] = max(max(dred[0], dred[1]), max(dred[2], dred[3]));
}

// ---------------------------------------------------------------------------
// P2: finish norms + lm column means
// ---------------------------------------------------------------------------
__global__ void p2_norms(const float* __restrict__ lm)
{
    int t = threadIdx.x;  // 512 threads, 1 block
    __shared__ float red[512];
    for (int c = 0; c < 3; c++) {
        float s = 0.f;
        for (int i = t; i < NODE; i += 512) s += g_rowSS[c * NODE + i];
        red[t] = s;
        __syncthreads();
        for (int off = 256; off; off >>= 1) {
            if (t < off) red[t] += red[t + off];
            __syncthreads();
        }
        if (t == 0) g_invnorm[c] = 1.0f / sqrtf(red[0]);
        __syncthreads();
    }
    if (t < NODE) {
        float s = 0.f;
        for (int o = 0; o < OUTN; o++) s += lm[o * NODE + t];
        g_colmean[t] = s * (1.0f / OUTN);
    }
}

// ---------------------------------------------------------------------------
// SIM: 50 blocks x 256 threads; warp w = node blockIdx*8+w, private smem slot.
// Timeline ring W: W[0..499]=hE0 reversed, W[500+t]=s2(t). Uniform delays.
// Far taps (d>=32): chunked gather every 32 steps into registers, read via
// shfl(aX, st). Near taps (d<32): rotating register window (seeded with the
// initial-history near contributions). Per-step smem traffic: ~3 small ops.
// ---------------------------------------------------------------------------
__global__ void __launch_bounds__(256) sim_kernel(
    const float* __restrict__ ext, const float* __restrict__ hx,
    const float* __restrict__ hE0, const float* __restrict__ theta)
{
    extern __shared__ char dsm[];
    int wid  = threadIdx.x >> 5;
    int lane = threadIdx.x & 31;
    int i = blockIdx.x * NPB + wid;       // node (50*8 = 400 exactly)

    char* base = dsm + wid * NODE_SMEM;
    float4* Ksm = (float4*)(base + OFF_KSM);
    float*  W   = (float*) (base + OFF_W);
    float*  Es  = (float*) (base + OFF_ES);

    const float4* Kg = g_K4 + (size_t)i * KBUF;
    for (int d = lane; d < KBUF; d += 32) Ksm[d] = Kg[d];
    // W[k] = hE0[499-k] for k in [0,500); runtime s2 goes to W[500+t]
    for (int k = lane; k < DMAXC; k += 32) W[k] = hE0[i * DMAXC + (DMAXC - 1 - k)];
    // transposed external input: Es[tr*STEPS+st] = ext[i][st][tr] -> Es[t] linear
    for (int s = lane; s < NSTEP; s += 32) {
        int st = s / TRS, tr = s - st * TRS;
        Es[tr * STEPS + st] = ext[(size_t)i * NSTEP + s];
    }
    __syncwarp();

    int dmax = g_ndmax[i];
    int pop = lane % 3;

    // scalar parameters
    float VL = reluf(theta[0]), VI = reluf(theta[1]), VE = reluf(theta[2]), VN = reluf(theta[3]);
    float amg = reluf(theta[4]), VR = reluf(theta[5]), ps = reluf(theta[6]);
    float gL = reluf(theta[7]), invC = rcpf(reluf(theta[8])), kap = reluf(theta[9]);
    float ggE = reluf(theta[10]), ggEsc = reluf(theta[11]);
    float ggI = reluf(theta[12]), ggIsc = reluf(theta[13]);
    float ggN = reluf(theta[14]), ggNsc = reluf(theta[15]);
    float gk  = reluf(theta[16]);
    float kki = reluf(theta[21]) * theta[23];
    float g_lc = reluf(theta[24]), g_fc = reluf(theta[25]), g_bc = reluf(theta[26]);

    float ABc = g_bc * g_invnorm[0], BBc = ABc * g_rs[i * 3 + 0];
    float AFc = g_fc * g_invnorm[1], BFc = AFc * g_rs[i * 3 + 1];
    float ALc = g_lc * g_invnorm[2], BLc = ALc * g_rs[i * 3 + 2];

    // per-lane population constants
    float cE, cI, cN, mU, mLr, Al, Bl;
    if (pop == 0)      { cE = ggE;   cI = ggI;   cN = ggN;   mU = kki; mLr = 1.f; Al = ALc; Bl = BLc; }
    else if (pop == 1) { cE = ggEsc; cI = ggIsc; cN = ggNsc; mU = 0.f; mLr = 0.f; Al = ABc; Bl = BBc; }
    else               { cE = gk;    cI = ggI;   cN = ggN;   mU = kki; mLr = 0.f; Al = AFc; Bl = BFc; }

    float nps2 = -ps * LOG2E, cs = ps * VR * LOG2E;
    float namg2 = -amg * LOG2E;

    float V  = hx[i * 12 + pop * 4 + 0];
    float gE = hx[i * 12 + pop * 4 + 1];
    float gI = hx[i * 12 + pop * 4 + 2];
    float gN = hx[i * 12 + pop * 4 + 3];

    // near taps: rotating window, lane l = partial for slot t+l (d<32).
    // Seed with initial history: P0(l) = sum_{d=l}^{31} K[d]*hE0[d-l]
    float4 Kn = Ksm[lane];
    float PB = 0.f, PF = 0.f, PL = 0.f;
    for (int d = lane; d < 32; d++) {
        float h = W[DMAXC + lane - 1 - d];   // = hE0[d-lane]
        float4 Kv = Ksm[d];
        PB = fmaf(Kv.x, h, PB);
        PF = fmaf(Kv.y, h, PF);
        PL = fmaf(Kv.z, h, PL);
    }

    float dtk = DTF * kap;
    int t = 0, stc = 0;
    for (int t0 = 0; t0 < NSTEP; t0 += 32) {
        __syncwarp();
        // far gather for slot t0+lane: sum_{d>=32} K[d] * W[500 + t0+lane-1-d]
        float aB = 0.f, aF = 0.f, aL = 0.f;
        {
            const float* Wx = W + (DMAXC + t0 + lane - 1);
            for (int d = 32; d <= dmax; d++) {
                float h = Wx[-d];
                float4 Kv = Ksm[d];
                aB = fmaf(Kv.x, h, aB);
                aF = fmaf(Kv.y, h, aF);
                aL = fmaf(Kv.z, h, aL);
            }
        }
        int nst = NSTEP - t0; if (nst > 32) nst = 32;
#pragma unroll 4
        for (int st = 0; st < nst; st++) {
            float s_ = rcpf(1.0f + ex2f(fmaf(nps2, V, cs)));
            float s0 = __shfl_sync(0xffffffffu, s_, 0);
            float s1 = __shfl_sync(0xffffffffu, s_, 1);
            float s2 = __shfl_sync(0xffffffffu, s_, 2);

            float mN = rcpf(fmaf(0.2f, ex2f(namg2 * V), 1.0f));
            float dV = (fmaf(gL, -VL - V,
                        fmaf(gE, VE - V,
                        fmaf(gI, -VI - V, (gN * mN) * (VN - V))))) * invC;

            // slot-t conv value = far (lane st) + near (lane 0)
            float fB = __shfl_sync(0xffffffffu, aB, st) + __shfl_sync(0xffffffffu, PB, 0);
            float fF = __shfl_sync(0xffffffffu, aF, st) + __shfl_sync(0xffffffffu, PF, 0);
            float fL = __shfl_sync(0xffffffffu, aL, st) + __shfl_sync(0xffffffffu, PL, 0);
            float a = (pop == 0) ? fL : ((pop == 1) ? fB : fF);
            float lr = fmaf(Al, a, -(Bl * s2));

            float u = Es[t];
            float se = (pop == 0) ? s2 : s0;
            float exc = fmaf(cE, se, lr);
            exc = fmaf(mU, u, exc);
            float nm = fmaf(cN, se, mLr * lr);
            float inh = cI * s1;

            V  = fmaf(DTF, dV, V);
            gE = fmaf(dtk, exc - gE, gE);
            gI = fmaf(dtk, inh - gI, gI);
            gN = fmaf(dtk, nm  - gN, gN);

            // rotate near window; lane 31 becomes fresh slot t+32
            float rB = __shfl_down_sync(0xffffffffu, PB, 1);
            float rF = __shfl_down_sync(0xffffffffu, PF, 1);
            float rL = __shfl_down_sync(0xffffffffu, PL, 1);
            bool fresh = (lane == 31);
            PB = fmaf(Kn.x, s2, fresh ? 0.f : rB);
            PF = fmaf(Kn.y, s2, fresh ? 0.f : rF);
            PL = fmaf(Kn.z, s2, fresh ? 0.f : rL);

            if (lane == 2) W[DMAXC + t] = s2;   // append s2(t) to timeline
            t++;
            if (++stc == STEPS) {
                stc = 0;
                if (lane == 2) g_Vsnap[(t / STEPS - 1) * NODE + i] = V;
            }
        }
    }
}

// ---------------------------------------------------------------------------
// EEG: warp per (trial, output); dual dot folds the column-mean subtraction.
// ---------------------------------------------------------------------------
__global__ void __launch_bounds__(256) eeg_kernel(
    const float* __restrict__ lm, const float* __restrict__ theta,
    float* __restrict__ out)
{
    int wpair = blockIdx.x * 8 + (threadIdx.x >> 5);   // 0..2559
    int lane = threadIdx.x & 31;
    int tr = wpair >> 6;
    int o  = wpair & 63;
    const float* Vs   = g_Vsnap + tr * NODE;
    const float* lrow = lm + o * NODE;

    float a0 = 0.f, a1 = 0.f, m0 = 0.f, m1 = 0.f;
#pragma unroll
    for (int k = 0; k < 7; k++) {          // 7*64 = 448 >= 400, last partial
        int i1 = lane + k * 64;
        int i2 = i1 + 32;
        if (i1 < NODE) {
            float v = Vs[i1];
            a0 = fmaf(lrow[i1], v, a0);
            m0 = fmaf(g_colmean[i1], v, m0);
        }
        if (i2 < NODE) {
            float v = Vs[i2];
            a1 = fmaf(lrow[i2], v, a1);
            m1 = fmaf(g_colmean[i2], v, m1);
        }
    }
    float acc = a0 + a1, m = m0 + m1;
#pragma unroll
    for (int off = 16; off; off >>= 1) {
        acc += __shfl_xor_sync(0xffffffffu, acc, off);
        m   += __shfl_xor_sync(0xffffffffu, m, off);
    }
    if (lane == 0) {
        float cy0 = theta[22], y0v = theta[19];
        out[tr * OUTN + o] = cy0 * (acc - m) - y0v;
    }
}

// ---------------------------------------------------------------------------
extern "C" void kernel_launch(void* const* d_in, const int* in_sizes, int n_in,
                              void* d_out, int out_size)
{
    const float* ext   = (const float*)d_in[0];
    const float* hx    = (const float*)d_in[1];
    const float* hE    = (const float*)d_in[2];
    const float* sc    = (const float*)d_in[3];
    const float* dist  = (const float*)d_in[4];
    const float* wbb   = (const float*)d_in[5];
    const float* wff   = (const float*)d_in[6];
    const float* wll   = (const float*)d_in[7];
    const float* lm    = (const float*)d_in[8];
    const float* theta = (const float*)d_in[9];
    float* out = (float*)d_out;

    cudaFuncSetAttribute(sim_kernel, cudaFuncAttributeMaxDynamicSharedMemorySize, SIM_SMEM);

    prep_kernel<<<NODE, 128>>>(wbb, wff, wll, sc, dist, theta);
    p2_norms<<<1, 512>>>(lm);
    sim_kernel<<<NODE / NPB, 256, SIM_SMEM>>>(ext, hx, hE, theta);
    eeg_kernel<<<(TRS * OUTN) / 8, 256>>>(lm, theta, out);
}

// round 7
// speedup vs baseline: 1.1874x; 1.1874x over previous
#include <cuda_runtime.h>
#include <math.h>

#define NODE  400
#define TRS   40
#define STEPS 10
#define NSTEP (TRS * STEPS)
#define OUTN  64
#define DMAXC 500
#define KBUF  512
#define DTF   0.1f
#define LOG2E 1.4426950408889634f

#define NPB   4        // nodes (warps) per sim block -> 100 blocks, 1 warp/SMSP
#define WN    904      // timeline ring: 500 initial + 400 steps (+pad)
// per-node dynamic smem slot layout (bytes)
#define OFF_KSM  0                        // float4[KBUF] = 8192
#define OFF_W    (KBUF * 16)              // float[WN]    = 3616
#define OFF_ES   (OFF_W + WN * 4)         // float[NSTEP] = 1600
#define NODE_SMEM 13440
#define SIM_SMEM (NODE_SMEM * NPB)        // 53760

// ---- persistent scratch (device globals; no allocation) ----
__device__ float  g_rowSS[3 * NODE];
__device__ float  g_invnorm[3];       // [b, f, l]
__device__ float  g_rs[NODE * 3];     // raw row sums [b,f,l] per node
__device__ float4 g_K4[NODE * KBUF];  // per-node delay histogram (x=b,y=f,z=l)
__device__ int    g_ndmax[NODE];
__device__ float  g_colmean[NODE];
__device__ float  g_Vsnap[TRS * NODE];
__device__ float  g_wllT[NODE * NODE];

__device__ __forceinline__ float reluf(float x) { return x > 0.f ? x : 0.f; }
__device__ __forceinline__ float ex2f(float x) { float y; asm("ex2.approx.f32 %0,%1;" : "=f"(y) : "f"(x)); return y; }
__device__ __forceinline__ float rcpf(float x) { float y; asm("rcp.approx.f32 %0,%1;" : "=f"(y) : "f"(x)); return y; }

// ---------------------------------------------------------------------------
// T0: transpose wll (32x32 tiles) so prep reads are coalesced.
// ---------------------------------------------------------------------------
__global__ void __launch_bounds__(256) transpose_kernel(const float* __restrict__ wll)
{
    __shared__ float tile[32][33];
    int bx = blockIdx.x % 13, by = blockIdx.x / 13;
    int x0 = bx * 32, y0 = by * 32;
    int tx = threadIdx.x & 31, ty8 = threadIdx.x >> 5;   // 8 rows per pass
    for (int r = ty8; r < 32; r += 8) {
        int y = y0 + r, x = x0 + tx;
        tile[r][tx] = (y < NODE && x < NODE) ? wll[y * NODE + x] : 0.f;
    }
    __syncthreads();
    for (int r = ty8; r < 32; r += 8) {
        int y = x0 + r, x = y0 + tx;   // transposed coords
        if (y < NODE && x < NODE) g_wllT[y * NODE + x] = tile[tx][r];
    }
}

// ---------------------------------------------------------------------------
// PREP: per-node weights, row sums, row sum-of-squares, delay histogram, dmax.
// sc is symmetric (0.5(A+A^T), zero diag) so sc[j,i] == sc[i,j].
// ---------------------------------------------------------------------------
__global__ void __launch_bounds__(128) prep_kernel(
    const float* __restrict__ wbb, const float* __restrict__ wff,
    const float* __restrict__ wll, const float* __restrict__ sc,
    const float* __restrict__ dist, const float* __restrict__ theta)
{
    int i = blockIdx.x;
    int tid = threadIdx.x;
    int w = tid >> 5, lane = tid & 31;
    __shared__ float4 w4[NODE];        // 6.4 KB
    __shared__ int    dly[NODE];       // 1.6 KB
    __shared__ float4 H[4][KBUF];      // 32 KB private histograms
    __shared__ float  red[6][128];     // 3 KB
    __shared__ int    dred[4];

    float mu = 0.1f + reluf(theta[20]);
    float ssb = 0.f, ssf = 0.f, ssl = 0.f, rb = 0.f, rf = 0.f, rl = 0.f;
    for (int j = tid; j < NODE; j += 128) {
        float scij = sc[i * NODE + j];
        float wb = __expf(wbb[i * NODE + j]) * scij;
        float wf = __expf(wff[i * NODE + j]) * scij;
        float wl = 0.5f * (__expf(wll[i * NODE + j]) + __expf(g_wllT[i * NODE + j])) * scij;
        int d = (int)(dist[i * NODE + j] / mu);   // accurate division like reference
        if (d < 0) d = 0;
        if (d > DMAXC - 1) d = DMAXC - 1;
        w4[j] = make_float4(wb, wf, wl, 0.f);
        dly[j] = d;
        ssb += wb * wb; ssf += wf * wf; ssl += wl * wl;
        rb += wb; rf += wf; rl += wl;
    }
    for (int d = tid; d < KBUF; d += 128) {
        float4 z = make_float4(0.f, 0.f, 0.f, 0.f);
        H[0][d] = z; H[1][d] = z; H[2][d] = z; H[3][d] = z;
    }
    red[0][tid] = ssb; red[1][tid] = ssf; red[2][tid] = ssl;
    red[3][tid] = rb;  red[4][tid] = rf;  red[5][tid] = rl;
    __syncthreads();
    for (int off = 64; off; off >>= 1) {
        if (tid < off) {
#pragma unroll
            for (int c = 0; c < 6; c++) red[c][tid] += red[c][tid + off];
        }
        __syncthreads();
    }
    if (tid == 0) {
        g_rowSS[0 * NODE + i] = red[0][0];
        g_rowSS[1 * NODE + i] = red[1][0];
        g_rowSS[2 * NODE + i] = red[2][0];
        g_rs[i * 3 + 0] = red[3][0];
        g_rs[i * 3 + 1] = red[4][0];
        g_rs[i * 3 + 2] = red[5][0];
    }

    // histogram: warp w scans j in [100w, 100w+100); lane owns (d&31)==lane bins
    int dmx = 0;
    int j0 = w * (NODE / 4);
    for (int jj = 0; jj < NODE / 4; jj++) {
        int j = j0 + jj;
        int d = dly[j];
        if ((d & 31) == lane) {
            float4 wv = w4[j];
            H[w][d].x += wv.x; H[w][d].y += wv.y; H[w][d].z += wv.z;
            dmx = d > dmx ? d : dmx;
        }
    }
#pragma unroll
    for (int off = 16; off; off >>= 1) dmx = max(dmx, __shfl_xor_sync(0xffffffffu, dmx, off));
    if (lane == 0) dred[w] = dmx;
    __syncthreads();

    float4* Kg = g_K4 + (size_t)i * KBUF;
    for (int d = tid; d < KBUF; d += 128) {
        float4 a = H[0][d], b = H[1][d], c = H[2][d], e = H[3][d];
        float4 r;
        r.x = ((a.x + b.x) + c.x) + e.x;
        r.y = ((a.y + b.y) + c.y) + e.y;
        r.z = ((a.z + b.z) + c.z) + e.z;
        r.w = 0.f;
        Kg[d] = r;
    }
    if (tid == 0) g_ndmax[i] = max(max(dred[0], dred[1]), max(dred[2], dred[3]));
}

// ---------------------------------------------------------------------------
// P2: finish norms + lm column means
// ---------------------------------------------------------------------------
__global__ void p2_norms(const float* __restrict__ lm)
{
    int t = threadIdx.x;  // 512 threads, 1 block
    __shared__ float red[512];
    for (int c = 0; c < 3; c++) {
        float s = 0.f;
        for (int i = t; i < NODE; i += 512) s += g_rowSS[c * NODE + i];
        red[t] = s;
        __syncthreads();
        for (int off = 256; off; off >>= 1) {
            if (t < off) red[t] += red[t + off];
            __syncthreads();
        }
        if (t == 0) g_invnorm[c] = 1.0f / sqrtf(red[0]);
        __syncthreads();
    }
    if (t < NODE) {
        float s = 0.f;
        for (int o = 0; o < OUTN; o++) s += lm[o * NODE + t];
        g_colmean[t] = s * (1.0f / OUTN);
    }
}

// ---------------------------------------------------------------------------
// SIM: 100 blocks x 128 threads -> 1 warp per SMSP on 100 SMs (400 SMSPs).
// Warp w = node blockIdx*4+w, private smem slot. Timeline ring W:
// W[0..499]=hE0 reversed, W[500+t]=s2(t). Far taps (d>=32): chunked gather
// every 32 steps; near taps (d<32): rotating register window.
// ---------------------------------------------------------------------------
__global__ void __launch_bounds__(128) sim_kernel(
    const float* __restrict__ ext, const float* __restrict__ hx,
    const float* __restrict__ hE0, const float* __restrict__ theta)
{
    extern __shared__ char dsm[];
    int wid  = threadIdx.x >> 5;
    int lane = threadIdx.x & 31;
    int i = blockIdx.x * NPB + wid;       // node (100*4 = 400 exactly)

    char* base = dsm + wid * NODE_SMEM;
    float4* Ksm = (float4*)(base + OFF_KSM);
    float*  W   = (float*) (base + OFF_W);
    float*  Es  = (float*) (base + OFF_ES);

    const float4* Kg = g_K4 + (size_t)i * KBUF;
    for (int d = lane; d < KBUF; d += 32) Ksm[d] = Kg[d];
    // W[k] = hE0[499-k] for k in [0,500); runtime s2 goes to W[500+t]
    for (int k = lane; k < DMAXC; k += 32) W[k] = hE0[i * DMAXC + (DMAXC - 1 - k)];
    // transposed external input: Es[tr*STEPS+st] = ext[i][st][tr] -> Es[t] linear
    for (int s = lane; s < NSTEP; s += 32) {
        int st = s / TRS, tr = s - st * TRS;
        Es[tr * STEPS + st] = ext[(size_t)i * NSTEP + s];
    }
    __syncwarp();

    int dmax = g_ndmax[i];
    int pop = lane % 3;

    // scalar parameters
    float VL = reluf(theta[0]), VI = reluf(theta[1]), VE = reluf(theta[2]), VN = reluf(theta[3]);
    float amg = reluf(theta[4]), VR = reluf(theta[5]), ps = reluf(theta[6]);
    float gL = reluf(theta[7]), invC = rcpf(reluf(theta[8])), kap = reluf(theta[9]);
    float ggE = reluf(theta[10]), ggEsc = reluf(theta[11]);
    float ggI = reluf(theta[12]), ggIsc = reluf(theta[13]);
    float ggN = reluf(theta[14]), ggNsc = reluf(theta[15]);
    float gk  = reluf(theta[16]);
    float kki = reluf(theta[21]) * theta[23];
    float g_lc = reluf(theta[24]), g_fc = reluf(theta[25]), g_bc = reluf(theta[26]);

    float ABc = g_bc * g_invnorm[0], BBc = ABc * g_rs[i * 3 + 0];
    float AFc = g_fc * g_invnorm[1], BFc = AFc * g_rs[i * 3 + 1];
    float ALc = g_lc * g_invnorm[2], BLc = ALc * g_rs[i * 3 + 2];

    // per-lane population constants
    float cE, cI, cN, mU, mLr, Al, Bl;
    if (pop == 0)      { cE = ggE;   cI = ggI;   cN = ggN;   mU = kki; mLr = 1.f; Al = ALc; Bl = BLc; }
    else if (pop == 1) { cE = ggEsc; cI = ggIsc; cN = ggNsc; mU = 0.f; mLr = 0.f; Al = ABc; Bl = BBc; }
    else               { cE = gk;    cI = ggI;   cN = ggN;   mU = kki; mLr = 0.f; Al = AFc; Bl = BFc; }

    float nps2 = -ps * LOG2E, cs = ps * VR * LOG2E;
    float namg2 = -amg * LOG2E;

    float V  = hx[i * 12 + pop * 4 + 0];
    float gE = hx[i * 12 + pop * 4 + 1];
    float gI = hx[i * 12 + pop * 4 + 2];
    float gN = hx[i * 12 + pop * 4 + 3];

    // near taps: rotating window, lane l = partial for slot t+l (d<32).
    // Seed with initial history: P0(l) = sum_{d=l}^{31} K[d]*hE0[d-l]
    float4 Kn = Ksm[lane];
    float PB = 0.f, PF = 0.f, PL = 0.f;
    for (int d = lane; d < 32; d++) {
        float h = W[DMAXC + lane - 1 - d];   // = hE0[d-lane]
        float4 Kv = Ksm[d];
        PB = fmaf(Kv.x, h, PB);
        PF = fmaf(Kv.y, h, PF);
        PL = fmaf(Kv.z, h, PL);
    }

    float dtk = DTF * kap;
    int t = 0, stc = 0;
    for (int t0 = 0; t0 < NSTEP; t0 += 32) {
        __syncwarp();
        // far gather for slot t0+lane: sum_{d>=32} K[d] * W[500 + t0+lane-1-d]
        float aB = 0.f, aF = 0.f, aL = 0.f;
        {
            const float* Wx = W + (DMAXC + t0 + lane - 1);
#pragma unroll 4
            for (int d = 32; d <= dmax; d++) {
                float h = Wx[-d];
                float4 Kv = Ksm[d];
                aB = fmaf(Kv.x, h, aB);
                aF = fmaf(Kv.y, h, aF);
                aL = fmaf(Kv.z, h, aL);
            }
        }
        int nst = NSTEP - t0; if (nst > 32) nst = 32;
#pragma unroll 4
        for (int st = 0; st < nst; st++) {
            float s_ = rcpf(1.0f + ex2f(fmaf(nps2, V, cs)));
            float s0 = __shfl_sync(0xffffffffu, s_, 0);
            float s1 = __shfl_sync(0xffffffffu, s_, 1);
            float s2 = __shfl_sync(0xffffffffu, s_, 2);

            float mN = rcpf(fmaf(0.2f, ex2f(namg2 * V), 1.0f));
            float dV = (fmaf(gL, -VL - V,
                        fmaf(gE, VE - V,
                        fmaf(gI, -VI - V, (gN * mN) * (VN - V))))) * invC;

            // slot-t conv value = far (lane st) + near (lane 0)
            float fB = __shfl_sync(0xffffffffu, aB, st) + __shfl_sync(0xffffffffu, PB, 0);
            float fF = __shfl_sync(0xffffffffu, aF, st) + __shfl_sync(0xffffffffu, PF, 0);
            float fL = __shfl_sync(0xffffffffu, aL, st) + __shfl_sync(0xffffffffu, PL, 0);
            float a = (pop == 0) ? fL : ((pop == 1) ? fB : fF);
            float lr = fmaf(Al, a, -(Bl * s2));

            float u = Es[t];
            float se = (pop == 0) ? s2 : s0;
            float exc = fmaf(cE, se, lr);
            exc = fmaf(mU, u, exc);
            float nm = fmaf(cN, se, mLr * lr);
            float inh = cI * s1;

            V  = fmaf(DTF, dV, V);
            gE = fmaf(dtk, exc - gE, gE);
            gI = fmaf(dtk, inh - gI, gI);
            gN = fmaf(dtk, nm  - gN, gN);

            // rotate near window; lane 31 becomes fresh slot t+32
            float rB = __shfl_down_sync(0xffffffffu, PB, 1);
            float rF = __shfl_down_sync(0xffffffffu, PF, 1);
            float rL = __shfl_down_sync(0xffffffffu, PL, 1);
            bool fresh = (lane == 31);
            PB = fmaf(Kn.x, s2, fresh ? 0.f : rB);
            PF = fmaf(Kn.y, s2, fresh ? 0.f : rF);
            PL = fmaf(Kn.z, s2, fresh ? 0.f : rL);

            if (lane == 2) W[DMAXC + t] = s2;   // append s2(t) to timeline
            t++;
            if (++stc == STEPS) {
                stc = 0;
                if (lane == 2) g_Vsnap[(t / STEPS - 1) * NODE + i] = V;
            }
        }
    }
}

// ---------------------------------------------------------------------------
// EEG: warp per (trial, output); dual dot folds the column-mean subtraction.
// ---------------------------------------------------------------------------
__global__ void __launch_bounds__(256) eeg_kernel(
    const float* __restrict__ lm, const float* __restrict__ theta,
    float* __restrict__ out)
{
    int wpair = blockIdx.x * 8 + (threadIdx.x >> 5);   // 0..2559
    int lane = threadIdx.x & 31;
    int tr = wpair >> 6;
    int o  = wpair & 63;
    const float* Vs   = g_Vsnap + tr * NODE;
    const float* lrow = lm + o * NODE;

    float a0 = 0.f, a1 = 0.f, m0 = 0.f, m1 = 0.f;
#pragma unroll
    for (int k = 0; k < 7; k++) {          // 7*64 = 448 >= 400, last partial
        int i1 = lane + k * 64;
        int i2 = i1 + 32;
        if (i1 < NODE) {
            float v = Vs[i1];
            a0 = fmaf(lrow[i1], v, a0);
            m0 = fmaf(g_colmean[i1], v, m0);
        }
        if (i2 < NODE) {
            float v = Vs[i2];
            a1 = fmaf(lrow[i2], v, a1);
            m1 = fmaf(g_colmean[i2], v, m1);
        }
    }
    float acc = a0 + a1, m = m0 + m1;
#pragma unroll
    for (int off = 16; off; off >>= 1) {
        acc += __shfl_xor_sync(0xffffffffu, acc, off);
        m   += __shfl_xor_sync(0xffffffffu, m, off);
    }
    if (lane == 0) {
        float cy0 = theta[22], y0v = theta[19];
        out[tr * OUTN + o] = cy0 * (acc - m) - y0v;
    }
}

// ---------------------------------------------------------------------------
extern "C" void kernel_launch(void* const* d_in, const int* in_sizes, int n_in,
                              void* d_out, int out_size)
{
    const float* ext   = (const float*)d_in[0];
    const float* hx    = (const float*)d_in[1];
    const float* hE    = (const float*)d_in[2];
    const float* sc    = (const float*)d_in[3];
    const float* dist  = (const float*)d_in[4];
    const float* wbb   = (const float*)d_in[5];
    const float* wff   = (const float*)d_in[6];
    const float* wll   = (const float*)d_in[7];
    const float* lm    = (const float*)d_in[8];
    const float* theta = (const float*)d_in[9];
    float* out = (float*)d_out;

    cudaFuncSetAttribute(sim_kernel, cudaFuncAttributeMaxDynamicSharedMemorySize, SIM_SMEM);

    transpose_kernel<<<13 * 13, 256>>>(wll);
    prep_kernel<<<NODE, 128>>>(wbb, wff, wll, sc, dist, theta);
    p2_norms<<<1, 512>>>(lm);
    sim_kernel<<<NODE / NPB, 128, SIM_SMEM>>>(ext, hx, hE, theta);
    eeg_kernel<<<(TRS * OUTN) / 8, 256>>>(lm, theta, out);
}

// round 8
// speedup vs baseline: 1.2907x; 1.0870x over previous
#include <cuda_runtime.h>
#include <math.h>

#define NODE  400
#define TRS   40
#define STEPS 10
#define NSTEP (TRS * STEPS)
#define OUTN  64
#define DMAXC 500
#define KBUF  512
#define KLEN  544      // KBUF + 32 zero pad (gather reads Ksm[lane + r], r <= dmax)
#define DTF   0.1f
#define LOG2E 1.4426950408889634f

#define NPB   4        // nodes (warps) per sim block -> 100 blocks, 1 warp/SMSP
#define WN    904      // timeline ring: 500 initial + 400 steps (+pad)
// per-node dynamic smem slot layout (bytes)
#define OFF_KSM  0                        // float4[KLEN] = 8704
#define OFF_W    (KLEN * 16)              // float[WN]    = 3616
#define OFF_ES   (OFF_W + WN * 4)         // float[NSTEP] = 1600
#define NODE_SMEM (OFF_ES + NSTEP * 4)    // 13920
#define SIM_SMEM (NODE_SMEM * NPB)        // 55680

// ---- persistent scratch (device globals; no allocation) ----
__device__ float  g_rowSS[3 * NODE];
__device__ float  g_invnorm[3];       // [b, f, l]
__device__ float  g_rs[NODE * 3];     // raw row sums [b,f,l] per node
__device__ float4 g_K4[NODE * KBUF];  // per-node delay histogram (x=b,y=f,z=l)
__device__ int    g_ndmax[NODE];
__device__ float  g_colmean[NODE];
__device__ float  g_Vsnap[TRS * NODE];
__device__ float  g_wllT[NODE * NODE];

__device__ __forceinline__ float reluf(float x) { return x > 0.f ? x : 0.f; }
__device__ __forceinline__ float ex2f(float x) { float y; asm("ex2.approx.f32 %0,%1;" : "=f"(y) : "f"(x)); return y; }
__device__ __forceinline__ float rcpf(float x) { float y; asm("rcp.approx.f32 %0,%1;" : "=f"(y) : "f"(x)); return y; }

// ---------------------------------------------------------------------------
// T0: transpose wll (32x32 tiles) so prep reads are coalesced.
// ---------------------------------------------------------------------------
__global__ void __launch_bounds__(256) transpose_kernel(const float* __restrict__ wll)
{
    __shared__ float tile[32][33];
    int bx = blockIdx.x % 13, by = blockIdx.x / 13;
    int x0 = bx * 32, y0 = by * 32;
    int tx = threadIdx.x & 31, ty8 = threadIdx.x >> 5;   // 8 rows per pass
    for (int r = ty8; r < 32; r += 8) {
        int y = y0 + r, x = x0 + tx;
        tile[r][tx] = (y < NODE && x < NODE) ? wll[y * NODE + x] : 0.f;
    }
    __syncthreads();
    for (int r = ty8; r < 32; r += 8) {
        int y = x0 + r, x = y0 + tx;   // transposed coords
        if (y < NODE && x < NODE) g_wllT[y * NODE + x] = tile[tx][r];
    }
}

// ---------------------------------------------------------------------------
// PREP: per-node weights, row sums, row sum-of-squares, delay histogram, dmax.
// sc is symmetric (0.5(A+A^T), zero diag) so sc[j,i] == sc[i,j].
// ---------------------------------------------------------------------------
__global__ void __launch_bounds__(128) prep_kernel(
    const float* __restrict__ wbb, const float* __restrict__ wff,
    const float* __restrict__ wll, const float* __restrict__ sc,
    const float* __restrict__ dist, const float* __restrict__ theta)
{
    int i = blockIdx.x;
    int tid = threadIdx.x;
    int w = tid >> 5, lane = tid & 31;
    __shared__ float4 w4[NODE];        // 6.4 KB
    __shared__ int    dly[NODE];       // 1.6 KB
    __shared__ float4 H[4][KBUF];      // 32 KB private histograms
    __shared__ float  red[6][128];     // 3 KB
    __shared__ int    dred[4];

    float mu = 0.1f + reluf(theta[20]);
    float ssb = 0.f, ssf = 0.f, ssl = 0.f, rb = 0.f, rf = 0.f, rl = 0.f;
    for (int j = tid; j < NODE; j += 128) {
        float scij = sc[i * NODE + j];
        float wb = __expf(wbb[i * NODE + j]) * scij;
        float wf = __expf(wff[i * NODE + j]) * scij;
        float wl = 0.5f * (__expf(wll[i * NODE + j]) + __expf(g_wllT[i * NODE + j])) * scij;
        int d = (int)(dist[i * NODE + j] / mu);   // accurate division like reference
        if (d < 0) d = 0;
        if (d > DMAXC - 1) d = DMAXC - 1;
        w4[j] = make_float4(wb, wf, wl, 0.f);
        dly[j] = d;
        ssb += wb * wb; ssf += wf * wf; ssl += wl * wl;
        rb += wb; rf += wf; rl += wl;
    }
    for (int d = tid; d < KBUF; d += 128) {
        float4 z = make_float4(0.f, 0.f, 0.f, 0.f);
        H[0][d] = z; H[1][d] = z; H[2][d] = z; H[3][d] = z;
    }
    red[0][tid] = ssb; red[1][tid] = ssf; red[2][tid] = ssl;
    red[3][tid] = rb;  red[4][tid] = rf;  red[5][tid] = rl;
    __syncthreads();
    for (int off = 64; off; off >>= 1) {
        if (tid < off) {
#pragma unroll
            for (int c = 0; c < 6; c++) red[c][tid] += red[c][tid + off];
        }
        __syncthreads();
    }
    if (tid == 0) {
        g_rowSS[0 * NODE + i] = red[0][0];
        g_rowSS[1 * NODE + i] = red[1][0];
        g_rowSS[2 * NODE + i] = red[2][0];
        g_rs[i * 3 + 0] = red[3][0];
        g_rs[i * 3 + 1] = red[4][0];
        g_rs[i * 3 + 2] = red[5][0];
    }

    // histogram: warp w scans j in [100w, 100w+100); lane owns (d&31)==lane bins
    int dmx = 0;
    int j0 = w * (NODE / 4);
    for (int jj = 0; jj < NODE / 4; jj++) {
        int j = j0 + jj;
        int d = dly[j];
        if ((d & 31) == lane) {
            float4 wv = w4[j];
            H[w][d].x += wv.x; H[w][d].y += wv.y; H[w][d].z += wv.z;
            dmx = d > dmx ? d : dmx;
        }
    }
#pragma unroll
    for (int off = 16; off; off >>= 1) dmx = max(dmx, __shfl_xor_sync(0xffffffffu, dmx, off));
    if (lane == 0) dred[w] = dmx;
    __syncthreads();

    float4* Kg = g_K4 + (size_t)i * KBUF;
    for (int d = tid; d < KBUF; d += 128) {
        float4 a = H[0][d], b = H[1][d], c = H[2][d], e = H[3][d];
        float4 r;
        r.x = ((a.x + b.x) + c.x) + e.x;
        r.y = ((a.y + b.y) + c.y) + e.y;
        r.z = ((a.z + b.z) + c.z) + e.z;
        r.w = 0.f;
        Kg[d] = r;
    }
    if (tid == 0) g_ndmax[i] = max(max(dred[0], dred[1]), max(dred[2], dred[3]));
}

// ---------------------------------------------------------------------------
// P2: finish norms + lm column means
// ---------------------------------------------------------------------------
__global__ void p2_norms(const float* __restrict__ lm)
{
    int t = threadIdx.x;  // 512 threads, 1 block
    __shared__ float red[512];
    for (int c = 0; c < 3; c++) {
        float s = 0.f;
        for (int i = t; i < NODE; i += 512) s += g_rowSS[c * NODE + i];
        red[t] = s;
        __syncthreads();
        for (int off = 256; off; off >>= 1) {
            if (t < off) red[t] += red[t + off];
            __syncthreads();
        }
        if (t == 0) g_invnorm[c] = 1.0f / sqrtf(red[0]);
        __syncthreads();
    }
    if (t < NODE) {
        float s = 0.f;
        for (int o = 0; o < OUTN; o++) s += lm[o * NODE + t];
        g_colmean[t] = s * (1.0f / OUTN);
    }
}

// ---------------------------------------------------------------------------
// SIM: 100 blocks x 128 threads -> 1 warp per SMSP on 100 SMs.
// Chunked slot-gather: at chunk t0, lane j holds G(j) = conv partial for slot
// t0+j over all KNOWN taps (d >= j). During steps, lanes j>k fold in the fresh
// s2 via one predicated LDS.128 + 3 FMA. At step k lane k's G is complete ->
// 3 broadcast shfls. No rotating window; per-step MIO ~ 6 shfl + 3 LDS/STS.
// ---------------------------------------------------------------------------
__global__ void __launch_bounds__(128) sim_kernel(
    const float* __restrict__ ext, const float* __restrict__ hx,
    const float* __restrict__ hE0, const float* __restrict__ theta)
{
    extern __shared__ char dsm[];
    int wid  = threadIdx.x >> 5;
    int lane = threadIdx.x & 31;
    int i = blockIdx.x * NPB + wid;       // node (100*4 = 400 exactly)

    char* base = dsm + wid * NODE_SMEM;
    float4* Ksm = (float4*)(base + OFF_KSM);
    float*  W   = (float*) (base + OFF_W);
    float*  Es  = (float*) (base + OFF_ES);

    const float4* Kg = g_K4 + (size_t)i * KBUF;
    for (int d = lane; d < KBUF; d += 32) Ksm[d] = Kg[d];
    for (int d = KBUF + lane; d < KLEN; d += 32) Ksm[d] = make_float4(0.f, 0.f, 0.f, 0.f);
    // W[k] = hE0[499-k] for k in [0,500); runtime s2 goes to W[500+t]
    for (int k = lane; k < DMAXC; k += 32) W[k] = hE0[i * DMAXC + (DMAXC - 1 - k)];
    // transposed external input: Es[tr*STEPS+st] = ext[i][st][tr] -> Es[t] linear
    for (int s = lane; s < NSTEP; s += 32) {
        int st = s / TRS, tr = s - st * TRS;
        Es[tr * STEPS + st] = ext[(size_t)i * NSTEP + s];
    }
    __syncwarp();

    int dmax = g_ndmax[i];
    int pop = lane % 3;

    // scalar parameters
    float VL = reluf(theta[0]), VI = reluf(theta[1]), VE = reluf(theta[2]), VN = reluf(theta[3]);
    float amg = reluf(theta[4]), VR = reluf(theta[5]), ps = reluf(theta[6]);
    float gL = reluf(theta[7]), invC = rcpf(reluf(theta[8])), kap = reluf(theta[9]);
    float ggE = reluf(theta[10]), ggEsc = reluf(theta[11]);
    float ggI = reluf(theta[12]), ggIsc = reluf(theta[13]);
    float ggN = reluf(theta[14]), ggNsc = reluf(theta[15]);
    float gk  = reluf(theta[16]);
    float kki = reluf(theta[21]) * theta[23];
    float g_lc = reluf(theta[24]), g_fc = reluf(theta[25]), g_bc = reluf(theta[26]);

    float ABc = g_bc * g_invnorm[0], BBc = ABc * g_rs[i * 3 + 0];
    float AFc = g_fc * g_invnorm[1], BFc = AFc * g_rs[i * 3 + 1];
    float ALc = g_lc * g_invnorm[2], BLc = ALc * g_rs[i * 3 + 2];

    // per-lane population constants
    float cE, cI, cN, mU, mLr, Al, Bl;
    if (pop == 0)      { cE = ggE;   cI = ggI;   cN = ggN;   mU = kki; mLr = 1.f; Al = ALc; Bl = BLc; }
    else if (pop == 1) { cE = ggEsc; cI = ggIsc; cN = ggNsc; mU = 0.f; mLr = 0.f; Al = ABc; Bl = BBc; }
    else               { cE = gk;    cI = ggI;   cN = ggN;   mU = kki; mLr = 0.f; Al = AFc; Bl = BFc; }

    float nps2 = -ps * LOG2E, cs = ps * VR * LOG2E;
    float namg2 = -amg * LOG2E;

    float V  = hx[i * 12 + pop * 4 + 0];
    float gE = hx[i * 12 + pop * 4 + 1];
    float gI = hx[i * 12 + pop * 4 + 2];
    float gN = hx[i * 12 + pop * 4 + 3];

    float dtk = DTF * kap;
    int t = 0, stc = 0;
    for (int t0 = 0; t0 < NSTEP; t0 += 32) {
        __syncwarp();
        // gather ALL known taps for slot t0+lane: G = sum_{d>=lane} K[d]*E(t0+lane-1-d)
        // with d = lane + r: E index = t0 - 1 - r  -> W[500 + t0 - 1 - r] (uniform!)
        float aB = 0.f, aF = 0.f, aL = 0.f;
        {
            const float* Wb = W + (DMAXC + t0 - 1);
#pragma unroll 4
            for (int r = 0; r <= dmax; r++) {
                float h = Wb[-r];                 // broadcast read
                float4 Kv = Ksm[lane + r];        // lane+r < 544 always
                aB = fmaf(Kv.x, h, aB);
                aF = fmaf(Kv.y, h, aF);
                aL = fmaf(Kv.z, h, aL);
            }
        }
        int nst = NSTEP - t0; if (nst > 32) nst = 32;
#pragma unroll 4
        for (int k = 0; k < nst; k++) {
            float s_ = rcpf(1.0f + ex2f(fmaf(nps2, V, cs)));
            float s0 = __shfl_sync(0xffffffffu, s_, 0);
            float s1 = __shfl_sync(0xffffffffu, s_, 1);
            float s2 = __shfl_sync(0xffffffffu, s_, 2);

            // completed conv value for slot t0+k lives in lane k
            float fB = __shfl_sync(0xffffffffu, aB, k);
            float fF = __shfl_sync(0xffffffffu, aF, k);
            float fL = __shfl_sync(0xffffffffu, aL, k);

            // fold fresh s2(t) into pending slots (lanes j>k, tap d = j-1-k)
            if (lane > k) {
                float4 Kv = Ksm[lane - 1 - k];
                aB = fmaf(Kv.x, s2, aB);
                aF = fmaf(Kv.y, s2, aF);
                aL = fmaf(Kv.z, s2, aL);
            }

            float mN = rcpf(fmaf(0.2f, ex2f(namg2 * V), 1.0f));
            float dV = (fmaf(gL, -VL - V,
                        fmaf(gE, VE - V,
                        fmaf(gI, -VI - V, (gN * mN) * (VN - V))))) * invC;

            float a = (pop == 0) ? fL : ((pop == 1) ? fB : fF);
            float lr = fmaf(Al, a, -(Bl * s2));

            float u = Es[t];
            float se = (pop == 0) ? s2 : s0;
            float exc = fmaf(cE, se, lr);
            exc = fmaf(mU, u, exc);
            float nm = fmaf(cN, se, mLr * lr);
            float inh = cI * s1;

            V  = fmaf(DTF, dV, V);
            gE = fmaf(dtk, exc - gE, gE);
            gI = fmaf(dtk, inh - gI, gI);
            gN = fmaf(dtk, nm  - gN, gN);

            if (lane == 2) W[DMAXC + t] = s2;   // append s2(t) to timeline
            t++;
            if (++stc == STEPS) {
                stc = 0;
                if (lane == 2) g_Vsnap[(t / STEPS - 1) * NODE + i] = V;
            }
        }
    }
}

// ---------------------------------------------------------------------------
// EEG: warp per (trial, output); dual dot folds the column-mean subtraction.
// ---------------------------------------------------------------------------
__global__ void __launch_bounds__(256) eeg_kernel(
    const float* __restrict__ lm, const float* __restrict__ theta,
    float* __restrict__ out)
{
    int wpair = blockIdx.x * 8 + (threadIdx.x >> 5);   // 0..2559
    int lane = threadIdx.x & 31;
    int tr = wpair >> 6;
    int o  = wpair & 63;
    const float* Vs   = g_Vsnap + tr * NODE;
    const float* lrow = lm + o * NODE;

    float a0 = 0.f, a1 = 0.f, m0 = 0.f, m1 = 0.f;
#pragma unroll
    for (int k = 0; k < 7; k++) {          // 7*64 = 448 >= 400, last partial
        int i1 = lane + k * 64;
        int i2 = i1 + 32;
        if (i1 < NODE) {
            float v = Vs[i1];
            a0 = fmaf(lrow[i1], v, a0);
            m0 = fmaf(g_colmean[i1], v, m0);
        }
        if (i2 < NODE) {
            float v = Vs[i2];
            a1 = fmaf(lrow[i2], v, a1);
            m1 = fmaf(g_colmean[i2], v, m1);
        }
    }
    float acc = a0 + a1, m = m0 + m1;
#pragma unroll
    for (int off = 16; off; off >>= 1) {
        acc += __shfl_xor_sync(0xffffffffu, acc, off);
        m   += __shfl_xor_sync(0xffffffffu, m, off);
    }
    if (lane == 0) {
        float cy0 = theta[22], y0v = theta[19];
        out[tr * OUTN + o] = cy0 * (acc - m) - y0v;
    }
}

// ---------------------------------------------------------------------------
extern "C" void kernel_launch(void* const* d_in, const int* in_sizes, int n_in,
                              void* d_out, int out_size)
{
    const float* ext   = (const float*)d_in[0];
    const float* hx    = (const float*)d_in[1];
    const float* hE    = (const float*)d_in[2];
    const float* sc    = (const float*)d_in[3];
    const float* dist  = (const float*)d_in[4];
    const float* wbb   = (const float*)d_in[5];
    const float* wff   = (const float*)d_in[6];
    const float* wll   = (const float*)d_in[7];
    const float* lm    = (const float*)d_in[8];
    const float* theta = (const float*)d_in[9];
    float* out = (float*)d_out;

    cudaFuncSetAttribute(sim_kernel, cudaFuncAttributeMaxDynamicSharedMemorySize, SIM_SMEM);

    transpose_kernel<<<13 * 13, 256>>>(wll);
    prep_kernel<<<NODE, 128>>>(wbb, wff, wll, sc, dist, theta);
    p2_norms<<<1, 512>>>(lm);
    sim_kernel<<<NODE / NPB, 128, SIM_SMEM>>>(ext, hx, hE, theta);
    eeg_kernel<<<(TRS * OUTN) / 8, 256>>>(lm, theta, out);
}